// round 6
// baseline (speedup 1.0000x reference)
#include <cuda_runtime.h>

#define NPIX    (512*512)
#define TILE    128
#define THREADS 512
#define NTILES  (NPIX/TILE)

#define WQ   0
#define WKT  8192
#define WV   12288
#define WO   16384
#define BO   24576
#define BI   24704
#define ZQ   24708                 // [128][132] z, then Qp/m per pair
#define QB   (ZQ + 128*132)        // [128][68]
#define OP   (QB + 128*68)         // [128][36]
#define SMF  (OP + 128*36)

typedef unsigned long long u64t;

__device__ __forceinline__ u64t pk2(float v){u64t r;asm("mov.b64 %0,{%1,%1};":"=l"(r):"f"(v));return r;}
__device__ __forceinline__ void upk2(u64t v,float&a,float&b){asm("mov.b64 {%0,%1},%2;":"=f"(a),"=f"(b):"l"(v));}
__device__ __forceinline__ void fma2(u64t&acc,u64t a,u64t b){asm("fma.rn.f32x2 %0,%1,%2,%0;":"+l"(acc):"l"(a),"l"(b));}
__device__ __forceinline__ void add2(u64t&acc,u64t b){asm("add.rn.f32x2 %0,%0,%1;":"+l"(acc):"l"(b));}

// 4-row x NC-u64col microkernel; rows j are jstr apart
template<int NC,int K>
__device__ __forceinline__ void gb(const float* zb,int jstr,const float* wb,int wstr,u64t (&acc)[4][NC]){
    #pragma unroll 4
    for(int k=0;k<K;k+=4){
        float4 zv[4];
        #pragma unroll
        for(int j=0;j<4;j++) zv[j]=*(const float4*)(zb+j*jstr+k);
        #pragma unroll
        for(int kk=0;kk<4;kk++){
            const float* wr=wb+(k+kk)*wstr;
            u64t wv[NC];
            #pragma unroll
            for(int c2=0;c2<NC/2;c2++){
                float4 w4=*(const float4*)(wr+4*c2);
                wv[2*c2]  =reinterpret_cast<const u64t*>(&w4)[0];
                wv[2*c2+1]=reinterpret_cast<const u64t*>(&w4)[1];
            }
            #pragma unroll
            for(int j=0;j<4;j++){
                u64t zz=pk2((&zv[j].x)[kk]);
                #pragma unroll
                for(int c=0;c<NC;c++) fma2(acc[j][c],zz,wv[c]);
            }
        }
    }
}

__global__ void __launch_bounds__(THREADS,1)
tpa_kernel(const float* __restrict__ t,const float* __restrict__ z,
           const float* __restrict__ mask,
           const float* __restrict__ Wq,const float* __restrict__ Wk,
           const float* __restrict__ Wv_,const float* __restrict__ Wo,
           const float* __restrict__ bo,float* __restrict__ out,int ntiles)
{
    extern __shared__ float sm[];
    const int tid=threadIdx.x;

    for(int i=tid;i<8192;i+=THREADS) sm[WQ+i]=Wq[i]*0.25f;
    for(int i=tid;i<4096;i+=THREADS) sm[WKT+i]=Wk[(i&63)*64+(i>>6)];
    for(int i=tid;i<4096;i+=THREADS) sm[WV+i]=Wv_[i];
    for(int i=tid;i<8192;i+=THREADS) sm[WO+i]=Wo[i];
    if(tid<128) sm[BO+tid]=bo[tid];
    if(tid<4)   sm[BI+tid]=1e5f*(mask[tid]-1.0f);
    __syncthreads();

    const int lane=tid&31, w=tid>>5;
    const int lpx=lane>>2, lcol=lane&3;
    // P1/P2: warp = 32px x 16col; thread px set {px1 + j*8}
    const int px1=(w&3)*32+lpx;
    const int c1 =(w>>2)*16+lcol*4;
    // P5: warp = 32px x 32col
    const int c5 =(w>>2)*32+lcol*8;
    // P4 (tid<256): px set {px4 + j*4}
    const int px4=(tid>>5)*16+((tid>>3)&3);
    const int hh4=(tid&7)>>2, cgl=tid&3;
    // P3
    const int p8=tid>>3, u=tid&7;

    for(int tile=blockIdx.x;tile<ntiles;tile+=gridDim.x){
        const int n0=tile*TILE;

        // P0: stage z [128][128] -> ZQ (stride 132)
        {
            const float4* zg=(const float4*)(z+(size_t)n0*128);
            #pragma unroll
            for(int i=0;i<8;i++){
                int e=tid+i*THREADS;
                *(float4*)(&sm[ZQ+(e>>5)*132+(e&31)*4])=zg[e];
            }
        }
        __syncthreads();

        // P1: Q[128][64] = z @ Wq'
        {
            u64t acc[4][2]={};
            gb<2,128>(&sm[ZQ+px1*132],8*132,&sm[WQ+c1],64,acc);
            #pragma unroll
            for(int j=0;j<4;j++)
                *(ulonglong2*)(&sm[QB+(px1+j*8)*68+c1])=make_ulonglong2(acc[j][0],acc[j][1]);
        }
        __syncthreads();

        #pragma unroll
        for(int pr=0;pr<2;pr++){
            // P2: Qp[px][hh*68+c] = Q[px][h*16+.] @ Wkt   (into ZQ)
            #pragma unroll
            for(int hh=0;hh<2;hh++){
                const int h=pr*2+hh;
                u64t acc[4][2]={};
                gb<2,16>(&sm[QB+px1*68+h*16],8*68,&sm[WKT+h*16*64+c1],64,acc);
                #pragma unroll
                for(int j=0;j<4;j++)
                    *(ulonglong2*)(&sm[ZQ+(px1+j*8)*132+hh*68+c1])=make_ulonglong2(acc[j][0],acc[j][1]);
            }
            __syncthreads();

            // P3: logits + softmax + m (in place), 8 thr/px, 2 px halves
            #pragma unroll
            for(int it=0;it<2;it++){
                const int px=it*64+p8, c0=u*8;
                const size_t ng=(size_t)n0+px;
                ulonglong2 tv[4][2];
                #pragma unroll
                for(int tt=0;tt<4;tt++){
                    const float* tp=t+((size_t)tt*NPIX+ng)*64+c0;
                    tv[tt][0]=*(const ulonglong2*)tp;
                    tv[tt][1]=*(const ulonglong2*)(tp+4);
                }
                float* qrow=&sm[ZQ+px*132];
                float lg[2][4];
                #pragma unroll
                for(int hh=0;hh<2;hh++){
                    ulonglong2 qa=*(const ulonglong2*)(qrow+hh*68+c0);
                    ulonglong2 qb=*(const ulonglong2*)(qrow+hh*68+c0+4);
                    #pragma unroll
                    for(int tt=0;tt<4;tt++){
                        u64t s=0;
                        fma2(s,qa.x,tv[tt][0].x); fma2(s,qa.y,tv[tt][0].y);
                        fma2(s,qb.x,tv[tt][1].x); fma2(s,qb.y,tv[tt][1].y);
                        float x0,x1; upk2(s,x0,x1); lg[hh][tt]=x0+x1;
                    }
                }
                #pragma unroll
                for(int off=4;off>=1;off>>=1)
                    #pragma unroll
                    for(int hh=0;hh<2;hh++)
                        #pragma unroll
                        for(int tt=0;tt<4;tt++)
                            lg[hh][tt]+=__shfl_xor_sync(0xffffffffu,lg[hh][tt],off,8);
                const float b0=sm[BI+0],b1=sm[BI+1],b2=sm[BI+2],b3=sm[BI+3];
                #pragma unroll
                for(int hh=0;hh<2;hh++){
                    float l0=lg[hh][0]+b0,l1=lg[hh][1]+b1,l2=lg[hh][2]+b2,l3=lg[hh][3]+b3;
                    float mx=fmaxf(fmaxf(l0,l1),fmaxf(l2,l3));
                    float e0=__expf(l0-mx),e1=__expf(l1-mx),e2=__expf(l2-mx),e3=__expf(l3-mx);
                    float inv=1.0f/(e0+e1+e2+e3);
                    u64t a0=pk2(e0*inv),a1=pk2(e1*inv),a2=pk2(e2*inv),a3=pk2(e3*inv);
                    u64t m0=0,m1=0,m2=0,m3=0;
                    fma2(m0,a0,tv[0][0].x); fma2(m1,a0,tv[0][0].y); fma2(m2,a0,tv[0][1].x); fma2(m3,a0,tv[0][1].y);
                    fma2(m0,a1,tv[1][0].x); fma2(m1,a1,tv[1][0].y); fma2(m2,a1,tv[1][1].x); fma2(m3,a1,tv[1][1].y);
                    fma2(m0,a2,tv[2][0].x); fma2(m1,a2,tv[2][0].y); fma2(m2,a2,tv[2][1].x); fma2(m3,a2,tv[2][1].y);
                    fma2(m0,a3,tv[3][0].x); fma2(m1,a3,tv[3][0].y); fma2(m2,a3,tv[3][1].x); fma2(m3,a3,tv[3][1].y);
                    *(ulonglong2*)(qrow+hh*68+c0)  =make_ulonglong2(m0,m1);
                    *(ulonglong2*)(qrow+hh*68+c0+4)=make_ulonglong2(m2,m3);
                }
            }
            __syncthreads();

            // P4: OP[px][hh*16+d] = m_h @ Wv_h (K=64); threads 0..255
            if(tid<256){
                const int h=pr*2+hh4;
                u64t acc[4][2]={};
                gb<2,64>(&sm[ZQ+px4*132+hh4*68],4*132,&sm[WV+h*16+cgl*4],64,acc);
                #pragma unroll
                for(int j=0;j<4;j++)
                    *(ulonglong2*)(&sm[OP+(px4+j*4)*36+hh4*16+cgl*4])=make_ulonglong2(acc[j][0],acc[j][1]);
            }
            __syncthreads();

            // P5: out[px][c5..+7] += OP @ Wo[pr*32..] (K=32); pair0 init with bo
            {
                u64t acc[4][4]={};
                gb<4,32>(&sm[OP+px1*36],8*36,&sm[WO+pr*32*128+c5],128,acc);
                #pragma unroll
                for(int j=0;j<4;j++){
                    float* og=out+((size_t)n0+px1+j*8)*128+c5;
                    u64t p0,p1,p2,p3;
                    if(pr==0){
                        float4 w0=*(const float4*)(&sm[BO+c5]);
                        float4 w1=*(const float4*)(&sm[BO+c5+4]);
                        p0=reinterpret_cast<const u64t*>(&w0)[0]; p1=reinterpret_cast<const u64t*>(&w0)[1];
                        p2=reinterpret_cast<const u64t*>(&w1)[0]; p3=reinterpret_cast<const u64t*>(&w1)[1];
                    }else{
                        ulonglong2 o0=*(const ulonglong2*)og, o1=*(const ulonglong2*)(og+4);
                        p0=o0.x; p1=o0.y; p2=o1.x; p3=o1.y;
                    }
                    add2(acc[j][0],p0); add2(acc[j][1],p1); add2(acc[j][2],p2); add2(acc[j][3],p3);
                    *(ulonglong2*)og    =make_ulonglong2(acc[j][0],acc[j][1]);
                    *(ulonglong2*)(og+4)=make_ulonglong2(acc[j][2],acc[j][3]);
                }
            }
        }
    }
}

extern "C" void kernel_launch(void* const* d_in,const int* in_sizes,int n_in,
                              void* d_out,int out_size)
{
    const float* t  =(const float*)d_in[0];
    const float* z  =(const float*)d_in[1];
    const float* mk =(const float*)d_in[2];
    const float* wq =(const float*)d_in[3];
    const float* wk =(const float*)d_in[4];
    const float* wv =(const float*)d_in[5];
    const float* wo =(const float*)d_in[6];
    const float* bo =(const float*)d_in[7];
    float* out=(float*)d_out;

    int nsm=148;
    cudaDeviceGetAttribute(&nsm,cudaDevAttrMultiProcessorCount,0);
    const size_t smem=(size_t)SMF*sizeof(float);
    cudaFuncSetAttribute(tpa_kernel,cudaFuncAttributeMaxDynamicSharedMemorySize,(int)smem);
    int grid=nsm<NTILES?nsm:NTILES;
    tpa_kernel<<<grid,THREADS,smem>>>(t,z,mk,wq,wk,wv,wo,bo,out,NTILES);
}

// round 8
// speedup vs baseline: 1.5578x; 1.5578x over previous
#include <cuda_runtime.h>
#include <cstdint>

#define NPIX (512*512)
#define THREADS 512
#define NTIL 2048

#define FQH 0
#define FQL 16384
#define FKH 32768
#define FKL 40960
#define FVH 49152
#define FVL 57344
#define FOH 65536
#define FOL 81920
#define QP  98304
#define MHB 98304
#define MLB 133120
#define ZH  98304
#define ZL2 133120
#define OHB 167936
#define OLB 178176
#define QHB 188416
#define QLB 206848
#define BOS 225280
#define SMB 225792

typedef unsigned long long u64t;

__device__ __forceinline__ uint32_t s2u(const void*p){uint32_t a;asm("{.reg .u64 t; cvta.to.shared.u64 t,%1; cvt.u32.u64 %0,t;}":"=r"(a):"l"(p));return a;}
__device__ __forceinline__ uint32_t pkbf(float lo,float hi){uint32_t r;asm("cvt.rn.bf16x2.f32 %0,%1,%2;":"=r"(r):"f"(hi),"f"(lo));return r;}
__device__ __forceinline__ void split2(float x0,float x1,uint32_t&h,uint32_t&l){
  h=pkbf(x0,x1);
  float h0=__uint_as_float(h<<16),h1=__uint_as_float(h&0xffff0000u);
  l=pkbf(x0-h0,x1-h1);
}
__device__ __forceinline__ void upk2(u64t v,float&a,float&b){asm("mov.b64 {%0,%1},%2;":"=f"(a),"=f"(b):"l"(v));}
__device__ __forceinline__ u64t pk2(float v){u64t r;asm("mov.b64 %0,{%1,%1};":"=l"(r):"f"(v));return r;}
__device__ __forceinline__ void fma2(u64t&acc,u64t a,u64t b){asm("fma.rn.f32x2 %0,%1,%2,%0;":"+l"(acc):"l"(a),"l"(b));}
__device__ __forceinline__ void mmabf(float*d,const uint32_t*A,uint32_t b0,uint32_t b1){
  asm("mma.sync.aligned.m16n8k16.row.col.f32.bf16.bf16.f32 {%0,%1,%2,%3},{%4,%5,%6,%7},{%8,%9},{%0,%1,%2,%3};"
   :"+f"(d[0]),"+f"(d[1]),"+f"(d[2]),"+f"(d[3]):"r"(A[0]),"r"(A[1]),"r"(A[2]),"r"(A[3]),"r"(b0),"r"(b1));
}
__device__ __forceinline__ void ldA(uint32_t base,int R,int S,int cw,int t5,uint32_t*A){
  int row=R+(t5&7)+((t5>>3)&1)*8;
  uint32_t ad=base+(uint32_t)(row*S+cw+((t5>>4)<<2))*4u;
  asm volatile("ldmatrix.sync.aligned.m8n8.x4.shared.b16 {%0,%1,%2,%3},[%4];":"=r"(A[0]),"=r"(A[1]),"=r"(A[2]),"=r"(A[3]):"r"(ad));
}

__global__ void __launch_bounds__(THREADS,1)
tpa_kernel(const float* __restrict__ t,const float* __restrict__ z,
           const float* __restrict__ mask,
           const float* __restrict__ Wq,const float* __restrict__ Wk,
           const float* __restrict__ Wv_,const float* __restrict__ Wo,
           const float* __restrict__ bo,float* __restrict__ out,int ntiles)
{
  extern __shared__ char sm[];
  const uint32_t sb=s2u(sm);
  const int tid=threadIdx.x,w=tid>>5,t5=tid&31,q=t5&3,r8=t5>>2;
  const int mt=w>>1,nh=w&1,R=mt*16;

  // ---- pre-shuffle weights into B-fragment arrays (hi/lo) ----
  for(int i=tid;i<4096;i+=THREADS){ // Wq: [ks8][nt8][lane][rg]
    int ks=i>>9,rm=i&511,nt=rm>>6,rm2=rm&63,ln=rm2>>1,rg=rm2&1;
    int k=ks*16+rg*8+2*(ln&3),n=nt*8+(ln>>2);
    uint32_t h,l; split2(Wq[k*64+n]*0.25f,Wq[(k+1)*64+n]*0.25f,h,l);
    uint32_t o=(uint32_t)(((ks*8+nt)*32+ln)<<3)+rg*4u;
    *(uint32_t*)(sm+FQH+o)=h; *(uint32_t*)(sm+FQL+o)=l;
  }
  for(int i=tid;i<2048;i+=THREADS){ // Wk^T per head: [h4][nt8][lane][rg]
    int hh=i>>9,rm=i&511,nt=rm>>6,rm2=rm&63,ln=rm2>>1,rg=rm2&1;
    int d=rg*8+2*(ln&3),c=nt*8+(ln>>2);
    uint32_t h,l; split2(Wk[c*64+hh*16+d],Wk[c*64+hh*16+d+1],h,l);
    uint32_t o=(uint32_t)(((hh*8+nt)*32+ln)<<3)+rg*4u;
    *(uint32_t*)(sm+FKH+o)=h; *(uint32_t*)(sm+FKL+o)=l;
  }
  for(int i=tid;i<2048;i+=THREADS){ // Wv per head: [h4][ks4][nt2][lane][rg]
    int hh=i>>9,rm=i&511,ks=rm>>7,rm1=rm&127,nt=rm1>>6,rm2=rm1&63,ln=rm2>>1,rg=rm2&1;
    int k=ks*16+rg*8+2*(ln&3),j=nt*8+(ln>>2);
    uint32_t h,l; split2(Wv_[k*64+hh*16+j],Wv_[(k+1)*64+hh*16+j],h,l);
    uint32_t o=(uint32_t)((((hh*4+ks)*2+nt)*32+ln)<<3)+rg*4u;
    *(uint32_t*)(sm+FVH+o)=h; *(uint32_t*)(sm+FVL+o)=l;
  }
  for(int i=tid;i<4096;i+=THREADS){ // Wo: [kg4][nt16][lane][rg]
    int kg=i>>10,rm=i&1023,nt=rm>>6,rm2=rm&63,ln=rm2>>1,rg=rm2&1;
    int k=kg*16+rg*8+2*(ln&3),n=nt*8+(ln>>2);
    uint32_t h,l; split2(Wo[k*128+n],Wo[(k+1)*128+n],h,l);
    uint32_t o=(uint32_t)(((kg*16+nt)*32+ln)<<3)+rg*4u;
    *(uint32_t*)(sm+FOH+o)=h; *(uint32_t*)(sm+FOL+o)=l;
  }
  if(tid<128) ((float*)(sm+BOS))[tid]=bo[tid];
  const float bi0=1e5f*(mask[0]-1.f),bi1=1e5f*(mask[1]-1.f),
              bi2=1e5f*(mask[2]-1.f),bi3=1e5f*(mask[3]-1.f);
  __syncthreads();

  const int p8=tid>>3,u=tid&7;

  for(int tile=blockIdx.x;tile<ntiles;tile+=gridDim.x){
    const int n0=tile*128;

    // s0: stage z -> packed bf16x2 hi/lo [128][68w]
    {
      int row=tid>>2,eq=tid&3;
      const float4* zg=(const float4*)(z+((size_t)(n0+row))*128+eq*32);
      #pragma unroll
      for(int j=0;j<8;j++){
        float4 v=zg[j];
        uint32_t h0,l0,h1,l1; split2(v.x,v.y,h0,l0); split2(v.z,v.w,h1,l1);
        uint32_t o=(uint32_t)(row*68+eq*16+2*j)*4u;
        *(uint2*)(sm+ZH+o)=make_uint2(h0,h1);
        *(uint2*)(sm+ZL2+o)=make_uint2(l0,l1);
      }
    }
    __syncthreads();

    // P1: Q = z @ Wq'  (K=128)
    {
      float acc[4][4]={};
      #pragma unroll
      for(int ks=0;ks<8;ks++){
        uint32_t Ah[4],Al[4];
        ldA(sb+ZH,R,68,ks*8,t5,Ah); ldA(sb+ZL2,R,68,ks*8,t5,Al);
        #pragma unroll
        for(int nt=0;nt<4;nt++){
          uint32_t fo=(uint32_t)(((ks*8+nh*4+nt)*32+t5)<<3);
          uint2 bh=*(const uint2*)(sm+FQH+fo),bl=*(const uint2*)(sm+FQL+fo);
          mmabf(acc[nt],Ah,bh.x,bh.y); mmabf(acc[nt],Ah,bl.x,bl.y); mmabf(acc[nt],Al,bh.x,bh.y);
        }
      }
      #pragma unroll
      for(int nt=0;nt<4;nt++){
        uint32_t h,l; int cwd=nh*16+nt*4+q;
        split2(acc[nt][0],acc[nt][1],h,l);
        uint32_t o0=(uint32_t)((R+r8)*36+cwd)*4u;
        *(uint32_t*)(sm+QHB+o0)=h; *(uint32_t*)(sm+QLB+o0)=l;
        split2(acc[nt][2],acc[nt][3],h,l);
        uint32_t o1=(uint32_t)((R+r8+8)*36+cwd)*4u;
        *(uint32_t*)(sm+QHB+o1)=h; *(uint32_t*)(sm+QLB+o1)=l;
      }
    }
    __syncthreads();

    float acc5[8][4]={};

    #pragma unroll
    for(int pr=0;pr<2;pr++){
      const int hgl=pr*2+nh;
      // P2: Qp_h = Q_h @ Wk_h (K=16) -> fp32 [128][130]
      {
        uint32_t Ah[4],Al[4];
        ldA(sb+QHB,R,36,hgl*8,t5,Ah); ldA(sb+QLB,R,36,hgl*8,t5,Al);
        #pragma unroll
        for(int nt=0;nt<8;nt++){
          float a[4]={};
          uint32_t fo=(uint32_t)(((hgl*8+nt)*32+t5)<<3);
          uint2 bh=*(const uint2*)(sm+FKH+fo),bl=*(const uint2*)(sm+FKL+fo);
          mmabf(a,Ah,bh.x,bh.y); mmabf(a,Ah,bl.x,bl.y); mmabf(a,Al,bh.x,bh.y);
          int cc=nh*64+nt*8+2*q;
          *(float2*)(sm+QP+(uint32_t)((R+r8)*130+cc)*4u)=make_float2(a[0],a[1]);
          *(float2*)(sm+QP+(uint32_t)((R+r8+8)*130+cc)*4u)=make_float2(a[2],a[3]);
        }
      }
      __syncthreads();

      // P3 pass1: logits + softmax -> aw (regs)
      float aw[2][2][4];
      #pragma unroll
      for(int it=0;it<2;it++){
        const int px=it*64+p8,c0=u*8; const size_t ng=(size_t)n0+px;
        u64t tv[4][4];
        #pragma unroll
        for(int tt=0;tt<4;tt++){
          const float* tp=t+((size_t)tt*NPIX+ng)*64+c0;
          tv[tt][0]=*(const u64t*)tp; tv[tt][1]=*(const u64t*)(tp+2);
          tv[tt][2]=*(const u64t*)(tp+4); tv[tt][3]=*(const u64t*)(tp+6);
        }
        const float* qr=(const float*)(sm+QP)+px*130+c0;
        float lg[2][4];
        #pragma unroll
        for(int hh=0;hh<2;hh++){
          u64t qa=*(const u64t*)(qr+hh*64),qb=*(const u64t*)(qr+hh*64+2),
               qc=*(const u64t*)(qr+hh*64+4),qd=*(const u64t*)(qr+hh*64+6);
          #pragma unroll
          for(int tt=0;tt<4;tt++){
            u64t s=0;
            fma2(s,qa,tv[tt][0]); fma2(s,qb,tv[tt][1]);
            fma2(s,qc,tv[tt][2]); fma2(s,qd,tv[tt][3]);
            float x0,x1; upk2(s,x0,x1); lg[hh][tt]=x0+x1;
          }
        }
        #pragma unroll
        for(int off=4;off>=1;off>>=1)
          #pragma unroll
          for(int hh=0;hh<2;hh++)
            #pragma unroll
            for(int tt=0;tt<4;tt++)
              lg[hh][tt]+=__shfl_xor_sync(0xffffffffu,lg[hh][tt],off,8);
        #pragma unroll
        for(int hh=0;hh<2;hh++){
          float l0=lg[hh][0]+bi0,l1=lg[hh][1]+bi1,l2=lg[hh][2]+bi2,l3=lg[hh][3]+bi3;
          float mx=fmaxf(fmaxf(l0,l1),fmaxf(l2,l3));
          float e0=__expf(l0-mx),e1=__expf(l1-mx),e2=__expf(l2-mx),e3=__expf(l3-mx);
          float inv=1.0f/(e0+e1+e2+e3);
          aw[it][hh][0]=e0*inv; aw[it][hh][1]=e1*inv; aw[it][hh][2]=e2*inv; aw[it][hh][3]=e3*inv;
        }
      }
      __syncthreads();

      // P3 pass2: m = a.t -> packed bf16x2 hi/lo [128][68w]
      #pragma unroll
      for(int it=0;it<2;it++){
        const int px=it*64+p8,c0=u*8; const size_t ng=(size_t)n0+px;
        u64t tv[4][4];
        #pragma unroll
        for(int tt=0;tt<4;tt++){
          const float* tp=t+((size_t)tt*NPIX+ng)*64+c0;
          tv[tt][0]=*(const u64t*)tp; tv[tt][1]=*(const u64t*)(tp+2);
          tv[tt][2]=*(const u64t*)(tp+4); tv[tt][3]=*(const u64t*)(tp+6);
        }
        #pragma unroll
        for(int hh=0;hh<2;hh++){
          u64t mm[4]={0,0,0,0};
          #pragma unroll
          for(int tt=0;tt<4;tt++){
            u64t a=pk2(aw[it][hh][tt]);
            fma2(mm[0],a,tv[tt][0]); fma2(mm[1],a,tv[tt][1]);
            fma2(mm[2],a,tv[tt][2]); fma2(mm[3],a,tv[tt][3]);
          }
          #pragma unroll
          for(int j=0;j<4;j++){
            float x0,x1; upk2(mm[j],x0,x1); uint32_t h,l; split2(x0,x1,h,l);
            uint32_t o=(uint32_t)(px*68+hh*32+u*4+j)*4u;
            *(uint32_t*)(sm+MHB+o)=h; *(uint32_t*)(sm+MLB+o)=l;
          }
        }
      }
      __syncthreads();

      // P4: O_h = m_h @ Wv_h (K=64, N=16)
      {
        float a[2][4]={};
        #pragma unroll
        for(int ks=0;ks<4;ks++){
          uint32_t Ah[4],Al[4];
          ldA(sb+MHB,R,68,nh*32+ks*8,t5,Ah); ldA(sb+MLB,R,68,nh*32+ks*8,t5,Al);
          #pragma unroll
          for(int nt=0;nt<2;nt++){
            uint32_t fo=(uint32_t)((((hgl*4+ks)*2+nt)*32+t5)<<3);
            uint2 bh=*(const uint2*)(sm+FVH+fo),bl=*(const uint2*)(sm+FVL+fo);
            mmabf(a[nt],Ah,bh.x,bh.y); mmabf(a[nt],Ah,bl.x,bl.y); mmabf(a[nt],Al,bh.x,bh.y);
          }
        }
        #pragma unroll
        for(int nt=0;nt<2;nt++){
          uint32_t h,l; int cwd=nh*8+nt*4+q;
          split2(a[nt][0],a[nt][1],h,l);
          uint32_t o0=(uint32_t)((R+r8)*20+cwd)*4u;
          *(uint32_t*)(sm+OHB+o0)=h; *(uint32_t*)(sm+OLB+o0)=l;
          split2(a[nt][2],a[nt][3],h,l);
          uint32_t o1=(uint32_t)((R+r8+8)*20+cwd)*4u;
          *(uint32_t*)(sm+OHB+o1)=h; *(uint32_t*)(sm+OLB+o1)=l;
        }
      }
      __syncthreads();

      // P5: out += O @ Wo[pr*32..] (K=32), accum in regs
      #pragma unroll
      for(int ks=0;ks<2;ks++){
        uint32_t Ah[4],Al[4];
        ldA(sb+OHB,R,20,ks*8,t5,Ah); ldA(sb+OLB,R,20,ks*8,t5,Al);
        #pragma unroll
        for(int nt=0;nt<8;nt++){
          uint32_t fo=(uint32_t)((((pr*2+ks)*16+nh*8+nt)*32+t5)<<3);
          uint2 bh=*(const uint2*)(sm+FOH+fo),bl=*(const uint2*)(sm+FOL+fo);
          mmabf(acc5[nt],Ah,bh.x,bh.y); mmabf(acc5[nt],Ah,bl.x,bl.y); mmabf(acc5[nt],Al,bh.x,bh.y);
        }
      }
      __syncthreads();
    }

    // epilogue: +bo, STG
    #pragma unroll
    for(int nt=0;nt<8;nt++){
      int c=nh*64+nt*8+2*q;
      float2 b=*(const float2*)(sm+BOS+(uint32_t)c*4u);
      float* o0=out+((size_t)(n0+R+r8))*128+c;
      *(float2*)o0=make_float2(acc5[nt][0]+b.x,acc5[nt][1]+b.y);
      *(float2*)(o0+8*128)=make_float2(acc5[nt][2]+b.x,acc5[nt][3]+b.y);
    }
    __syncthreads();
  }
}

extern "C" void kernel_launch(void* const* d_in,const int* in_sizes,int n_in,
                              void* d_out,int out_size)
{
  const float* t  =(const float*)d_in[0];
  const float* z  =(const float*)d_in[1];
  const float* mk =(const float*)d_in[2];
  const float* wq =(const float*)d_in[3];
  const float* wk =(const float*)d_in[4];
  const float* wv =(const float*)d_in[5];
  const float* wo =(const float*)d_in[6];
  const float* bo =(const float*)d_in[7];
  float* out=(float*)d_out;
  int nsm=148;
  cudaDeviceGetAttribute(&nsm,cudaDevAttrMultiProcessorCount,0);
  cudaFuncSetAttribute(tpa_kernel,cudaFuncAttributeMaxDynamicSharedMemorySize,SMB);
  int grid=nsm<NTIL?nsm:NTIL;
  tpa_kernel<<<grid,THREADS,SMB>>>(t,z,mk,wq,wk,wv,wo,bo,out,NTIL);
}